// round 10
// baseline (speedup 1.0000x reference)
#include <cuda_runtime.h>
#include <cstdint>
#include <cmath>

#define BB 512
#define NN 1000
#define CC 50
#define CCP 51              // pitch for transposed cluster tile (odd -> conflict-free)
#define EE 128
#define HH 8
#define DD 16
#define SPLIT 8
#define NPS (NN/SPLIT)
#define NEGV (-1e9f)
#define FUSE_ROWS (6*EE)    // 768 rows of weight prep work

// scratch (no cudaMalloc allowed)
__device__ float g_part[BB*SPLIT*2*EE];   // [b][split][{mask, mask|cmask}][e]
__device__ float g_Wqf [3*EE*EE];         // Wq @ mha_Wq   (384 x 128), [i][j]
__device__ float g_WkfT[EE*EE];           // (Wk @ mha_Wk)^T : [j][e]
__device__ float g_Wvf [EE*EE];           // Wv @ mha_Wv    : [e][j]
__device__ float g_WoKs[EE*EE];           // Wo @ Wks^T     : [j][e]

// ---------------------------------------------------------------------------
// Kernel 1: masked reduction (ballot-compacted, branch-free loads) + weight
// prep folded into the same grid. grid (BB, SPLIT+2), 128 threads.
// ---------------------------------------------------------------------------
__global__ void __launch_bounds__(128) k_pre(
    const float* __restrict__ nodes,
    const int* __restrict__ mask, const int* __restrict__ cmask,
    const float* __restrict__ Wq, const float* __restrict__ Wk,
    const float* __restrict__ Wv, const float* __restrict__ Wks,
    const float* __restrict__ Wo,
    const float* __restrict__ mWq, const float* __restrict__ mWk,
    const float* __restrict__ mWv)
{
    const int b = blockIdx.x, y = blockIdx.y, t = threadIdx.x;
    const int warp = t >> 5, lane = t & 31;

    if (y >= SPLIT) {
        // ---- weight prep planes (overlap with reduction planes) ----
        int fr = (y - SPLIT)*BB + b;
        if (fr >= FUSE_ROWS) return;
        if (fr < 3*EE) {
            const float* a_ = Wq + fr*EE;
            float s0=0.f,s1=0.f,s2=0.f,s3=0.f;
            #pragma unroll 8
            for (int e = 0; e < EE; e += 4) {
                s0 += a_[e  ] * mWq[(e  )*EE + t];
                s1 += a_[e+1] * mWq[(e+1)*EE + t];
                s2 += a_[e+2] * mWq[(e+2)*EE + t];
                s3 += a_[e+3] * mWq[(e+3)*EE + t];
            }
            g_Wqf[fr*EE + t] = (s0+s1)+(s2+s3);
        } else if (fr < 4*EE) {
            const int e0 = fr - 3*EE;
            const float* a_ = Wk + e0*EE;
            float s0=0.f,s1=0.f,s2=0.f,s3=0.f;
            #pragma unroll 8
            for (int x = 0; x < EE; x += 4) {
                s0 += a_[x  ] * mWk[(x  )*EE + t];
                s1 += a_[x+1] * mWk[(x+1)*EE + t];
                s2 += a_[x+2] * mWk[(x+2)*EE + t];
                s3 += a_[x+3] * mWk[(x+3)*EE + t];
            }
            g_WkfT[t*EE + e0] = (s0+s1)+(s2+s3);   // transposed
        } else if (fr < 5*EE) {
            const int e0 = fr - 4*EE;
            const float* a_ = Wv + e0*EE;
            float s0=0.f,s1=0.f,s2=0.f,s3=0.f;
            #pragma unroll 8
            for (int x = 0; x < EE; x += 4) {
                s0 += a_[x  ] * mWv[(x  )*EE + t];
                s1 += a_[x+1] * mWv[(x+1)*EE + t];
                s2 += a_[x+2] * mWv[(x+2)*EE + t];
                s3 += a_[x+3] * mWv[(x+3)*EE + t];
            }
            g_Wvf[e0*EE + t] = (s0+s1)+(s2+s3);
        } else {
            // WoKs[j][e] = sum_f Wo[j][f] * Wks[e][f]
            const int j = fr - 5*EE;
            __shared__ float sWo[EE];
            sWo[t] = Wo[j*EE + t];
            __syncthreads();
            const float* wk = Wks + t*EE;     // thread's own Wks row (L2-served)
            float s0=0.f,s1=0.f,s2=0.f,s3=0.f;
            #pragma unroll 8
            for (int f = 0; f < EE; f += 4) {
                s0 += sWo[f  ] * wk[f  ];
                s1 += sWo[f+1] * wk[f+1];
                s2 += sWo[f+2] * wk[f+2];
                s3 += sWo[f+3] * wk[f+3];
            }
            g_WoKs[j*EE + t] = (s0+s1)+(s2+s3);
        }
        return;
    }

    // ---- reduction plane: rows [y*NPS, (y+1)*NPS) of batch b ----
    __shared__ uint8_t sC[NPS];
    __shared__ short   sList[NPS];
    __shared__ int     sWcnt[4], sWoff[4], sCnt;
    __shared__ float4  sR0[4][32], sR1[4][32];

    const int* m  = mask  + b*NN + y*NPS;
    const int* cm = cmask + b*NN + y*NPS;
    const bool keep = (t < NPS) && (m[t] == 0);
    if (t < NPS) sC[t] = (uint8_t)(cm[t] != 0);

    // ballot compaction of unmasked row indices
    unsigned bal = __ballot_sync(0xffffffffu, keep);
    if (lane == 0) sWcnt[warp] = __popc(bal);
    __syncthreads();
    if (t == 0) {
        int s = 0;
        #pragma unroll
        for (int w = 0; w < 4; w++) { sWoff[w] = s; s += sWcnt[w]; }
        sCnt = s;
    }
    __syncthreads();
    if (keep)
        sList[sWoff[warp] + __popc(bal & ((1u << lane) - 1u))] = (short)t;
    __syncthreads();

    const int cnt = sCnt;
    const float4* base = (const float4*)(nodes + ((size_t)b*NN + (size_t)y*NPS)*EE);

    float4 a0 = make_float4(0.f,0.f,0.f,0.f);
    float4 a1 = make_float4(0.f,0.f,0.f,0.f);
    int i = warp;
    for (; i + 4 < cnt; i += 8) {           // 2 loads in flight, branch-free
        int r0 = sList[i], r1 = sList[i+4];
        float4 v0 = __ldg(base + r0*32 + lane);
        float4 v1 = __ldg(base + r1*32 + lane);
        bool c0 = sC[r0], c1 = sC[r1];
        a0.x += v0.x; a0.y += v0.y; a0.z += v0.z; a0.w += v0.w;
        if (!c0) { a1.x += v0.x; a1.y += v0.y; a1.z += v0.z; a1.w += v0.w; }
        a0.x += v1.x; a0.y += v1.y; a0.z += v1.z; a0.w += v1.w;
        if (!c1) { a1.x += v1.x; a1.y += v1.y; a1.z += v1.z; a1.w += v1.w; }
    }
    if (i < cnt) {
        int r0 = sList[i];
        float4 v0 = __ldg(base + r0*32 + lane);
        bool c0 = sC[r0];
        a0.x += v0.x; a0.y += v0.y; a0.z += v0.z; a0.w += v0.w;
        if (!c0) { a1.x += v0.x; a1.y += v0.y; a1.z += v0.z; a1.w += v0.w; }
    }
    sR0[warp][lane] = a0;
    sR1[warp][lane] = a1;
    __syncthreads();

    const float* p0 = (const float*)sR0;
    const float* p1 = (const float*)sR1;
    float s0 = p0[t] + p0[128 + t] + p0[256 + t] + p0[384 + t];
    float s1 = p1[t] + p1[128 + t] + p1[256 + t] + p1[384 + t];
    int idx = (b*SPLIT + y)*2*EE + t;
    g_part[idx]      = s0;
    g_part[idx + EE] = s1;
}

// ---------------------------------------------------------------------------
// Kernel 2: math chain per batch. 256 threads/block. (R6-proven structure,
// with Wo+Wks stages merged into one WoKs stage.)
// ---------------------------------------------------------------------------
__global__ void __launch_bounds__(256) k_main(
    const float* __restrict__ depot, const float* __restrict__ CE,
    const float* __restrict__ cur,   const float* __restrict__ augc,
    const float* __restrict__ gein,
    const int* __restrict__ isnew, const int* __restrict__ vcm_g,
    const int* __restrict__ guid_in, float* __restrict__ out)
{
    const int b = blockIdx.x, t = threadIdx.x;
    const int t2 = t & 127, half = t >> 7;
    const int warp = t >> 5, lane = t & 31;

    __shared__ float sCET[EE*CCP];     // transposed cluster embeddings
    __shared__ float sCtx[3*EE];
    __shared__ float sUC[EE];
    __shared__ float sP2[2][EE];       // split-K partials (reused per stage)
    __shared__ float sQ[EE];
    __shared__ float sKQ[HH*EE];
    __shared__ float sSc[HH*CC];
    __shared__ float sAt[HH*CC];
    __shared__ float sAce[HH*EE];
    __shared__ float sGl[EE];
    __shared__ float sW2[EE];
    __shared__ float sLgP[4][CC];
    __shared__ float sLg[CC];
    __shared__ int   sVcm[CC];
    __shared__ float sMax, sLse;
    __shared__ int   sArg;

    // ---- load cluster embeddings transposed; half owns 25 c's, e = t2 ----
    {
        const float* src = CE + (size_t)b*CC*EE;
        #pragma unroll
        for (int cc = 0; cc < 25; cc++) {
            int c = half*25 + cc;
            sCET[t2*CCP + c] = src[c*EE + t2];
        }
    }

    // ---- combine reduction partials: half 0 -> um, half 1 -> uc ----
    {
        float a = 0.f;
        #pragma unroll
        for (int s = 0; s < SPLIT; s++)
            a += g_part[(b*SPLIT + s)*2*EE + half*EE + t2];
        a *= (1.f/NN);
        if (half == 0) sCtx[t2] = a; else sUC[t2] = a;
    }
    if (half == 0) sCtx[EE + t2]   = cur[b*EE + t2];
    else           sCtx[2*EE + t2] = depot[b*EE + t2];
    if (t < CC) sVcm[t] = (vcm_g[b*CC + t] != 0);
    __syncthreads();

    if (t == 0) {                      // vcm[0] = !all(vcm[1:])
        int all = 1;
        for (int c = 1; c < CC; c++) all &= (sVcm[c] != 0);
        sVcm[0] = !all;
    }

    // ---- q projection, split-K over halves (192 MACs each, 4 accs) ----
    {
        const int i0 = half*192;
        float a0=0.f,a1=0.f,a2=0.f,a3=0.f;
        #pragma unroll 4
        for (int i = 0; i < 192; i += 4) {
            a0 += sCtx[i0+i  ] * g_Wqf[(i0+i  )*EE + t2];
            a1 += sCtx[i0+i+1] * g_Wqf[(i0+i+1)*EE + t2];
            a2 += sCtx[i0+i+2] * g_Wqf[(i0+i+2)*EE + t2];
            a3 += sCtx[i0+i+3] * g_Wqf[(i0+i+3)*EE + t2];
        }
        sP2[half][t2] = (a0+a1)+(a2+a3);
    }
    __syncthreads();
    if (half == 0) sQ[t2] = sP2[0][t2] + sP2[1][t2];
    __syncthreads();

    // ---- kq[h][e]: 1024 outputs over 256 threads (4 each), 16 MACs ----
    #pragma unroll
    for (int k = 0; k < 4; k++) {
        int idx = t + 256*k;
        int h = idx >> 7, e = idx & 127;
        float a0=0.f,a1=0.f;
        #pragma unroll
        for (int d = 0; d < DD; d += 2) {
            a0 += sQ[h*DD + d  ] * g_WkfT[(h*DD + d  )*EE + e];
            a1 += sQ[h*DD + d+1] * g_WkfT[(h*DD + d+1)*EE + e];
        }
        sKQ[h*EE + e] = a0 + a1;
    }
    __syncthreads();

    // ---- scores: 400 outputs, 128 MACs, 4 accs ----
    for (int idx = t; idx < HH*CC; idx += 256) {
        int h = idx / CC, c = idx % CC;
        float a0=0.f,a1=0.f,a2=0.f,a3=0.f;
        #pragma unroll 4
        for (int e = 0; e < EE; e += 4) {
            a0 += sCET[(e  )*CCP + c] * sKQ[h*EE + e  ];
            a1 += sCET[(e+1)*CCP + c] * sKQ[h*EE + e+1];
            a2 += sCET[(e+2)*CCP + c] * sKQ[h*EE + e+2];
            a3 += sCET[(e+3)*CCP + c] * sKQ[h*EE + e+3];
        }
        float a = ((a0+a1)+(a2+a3)) * 0.25f;   // 1/sqrt(16)
        if (sVcm[c]) a = NEGV;
        sSc[h*CC + c] = a;
    }
    __syncthreads();

    // ---- softmax: warp h owns head h ----
    {
        int h = warp;
        float v0 = sSc[h*CC + lane];
        float v1 = (lane < CC-32) ? sSc[h*CC + lane + 32] : -3e38f;
        float mx = fmaxf(v0, v1);
        #pragma unroll
        for (int o = 16; o > 0; o >>= 1)
            mx = fmaxf(mx, __shfl_xor_sync(0xffffffffu, mx, o));
        float e0 = expf(v0 - mx);
        float e1 = (lane < CC-32) ? expf(v1 - mx) : 0.f;
        float sm = e0 + e1;
        #pragma unroll
        for (int o = 16; o > 0; o >>= 1)
            sm += __shfl_xor_sync(0xffffffffu, sm, o);
        float inv = 1.f / sm;
        sAt[h*CC + lane] = e0 * inv;
        if (lane < CC-32) sAt[h*CC + lane + 32] = e1 * inv;
    }
    __syncthreads();

    // ---- a_ce[h][e]: 1024 outputs over 256 threads, 50 MACs, 2 accs ----
    #pragma unroll
    for (int k = 0; k < 4; k++) {
        int idx = t + 256*k;
        int h = idx >> 7, e = idx & 127;
        float a0=0.f,a1=0.f;
        #pragma unroll 5
        for (int c = 0; c < CC; c += 2) {
            a0 += sAt[h*CC + c  ] * sCET[e*CCP + c  ];
            a1 += sAt[h*CC + c+1] * sCET[e*CCP + c+1];
        }
        sAce[h*EE + e] = a0 + a1;
    }
    __syncthreads();

    // ---- glimpse[j=t2]: 128-MAC split-K over halves (h = j/16) ----
    {
        int h = t2 / DD;
        const int e0 = half*64;
        float a0=0.f,a1=0.f,a2=0.f,a3=0.f;
        #pragma unroll 4
        for (int e = 0; e < 64; e += 4) {
            a0 += sAce[h*EE + e0+e  ] * g_Wvf[(e0+e  )*EE + t2];
            a1 += sAce[h*EE + e0+e+1] * g_Wvf[(e0+e+1)*EE + t2];
            a2 += sAce[h*EE + e0+e+2] * g_Wvf[(e0+e+2)*EE + t2];
            a3 += sAce[h*EE + e0+e+3] * g_Wvf[(e0+e+3)*EE + t2];
        }
        sP2[half][t2] = (a0+a1)+(a2+a3);
    }
    __syncthreads();
    if (half == 0) sGl[t2] = sP2[0][t2] + sP2[1][t2];
    __syncthreads();

    // ---- w2[e=t2] = sum_j gl[j] * WoKs[j][e]: split-K over halves ----
    {
        const int j0 = half*64;
        float a0=0.f,a1=0.f,a2=0.f,a3=0.f;
        #pragma unroll 4
        for (int j = 0; j < 64; j += 4) {
            a0 += sGl[j0+j  ] * g_WoKs[(j0+j  )*EE + t2];
            a1 += sGl[j0+j+1] * g_WoKs[(j0+j+1)*EE + t2];
            a2 += sGl[j0+j+2] * g_WoKs[(j0+j+2)*EE + t2];
            a3 += sGl[j0+j+3] * g_WoKs[(j0+j+3)*EE + t2];
        }
        sP2[half][t2] = (a0+a1)+(a2+a3);
    }
    __syncthreads();
    if (half == 0) sW2[t2] = sP2[0][t2] + sP2[1][t2];
    __syncthreads();

    // ---- logit[c]: 50 outputs, split over 4 quarters of e ----
    {
        int c = t & 63, q4 = t >> 6;
        if (c < CC) {
            const int e0 = q4*32;
            float a0=0.f,a1=0.f;
            #pragma unroll 4
            for (int e = 0; e < 32; e += 2) {
                a0 += sCET[(e0+e  )*CCP + c] * sW2[e0+e  ];
                a1 += sCET[(e0+e+1)*CCP + c] * sW2[e0+e+1];
            }
            sLgP[q4][c] = a0 + a1;
        }
    }
    __syncthreads();
    if (t < CC) {
        float a = (sLgP[0][t] + sLgP[1][t]) + (sLgP[2][t] + sLgP[3][t]);
        a *= 0.08838834764831845f;     // 1/sqrt(128)
        a = tanhf(a) * 10.f;
        if (sVcm[t]) a = NEGV;
        sLg[t] = a;
    }
    __syncthreads();

    // ---- argmax (first-index ties) + logsumexp, warp 0 via shfl ----
    if (warp == 0) {
        float v0 = sLg[lane];
        float v1 = (lane < CC-32) ? sLg[lane + 32] : -3e38f;
        float v = v0; int ix = lane;
        if (v1 > v) { v = v1; ix = lane + 32; }
        #pragma unroll
        for (int o = 16; o > 0; o >>= 1) {
            float ov = __shfl_xor_sync(0xffffffffu, v, o);
            int   oi = __shfl_xor_sync(0xffffffffu, ix, o);
            if (ov > v || (ov == v && oi < ix)) { v = ov; ix = oi; }
        }
        float mx = v;
        float sm = expf(v0 - mx) + ((lane < CC-32) ? expf(v1 - mx) : 0.f);
        #pragma unroll
        for (int o = 16; o > 0; o >>= 1)
            sm += __shfl_xor_sync(0xffffffffu, sm, o);
        if (lane == 0) { sMax = mx; sLse = logf(sm); sArg = ix; }
    }
    __syncthreads();

    const int  guid = sArg;
    const bool isn  = isnew[b] != 0;
    const float ge  = sCET[t2*CCP + guid];

    const size_t OFF1 = (size_t)BB*4*EE;            // guid_embed_out
    const size_t OFF2 = OFF1 + (size_t)BB*EE;       // guid_out
    const size_t OFF3 = OFF2 + BB;                  // clu_prob

    float* ao = out + (size_t)b*4*EE;
    const float* ac = augc + (size_t)b*4*EE;
    if (half == 0) {
        ao[t2]        = isn ? sUC[t2]          : ac[t2];
        ao[2*EE + t2] = isn ? ge               : ac[2*EE + t2];
        out[OFF1 + (size_t)b*EE + t2] = isn ? ge : gein[b*EE + t2];
    } else {
        ao[EE + t2]   = isn ? sCtx[EE + t2]    : ac[EE + t2];
        ao[3*EE + t2] = isn ? sCtx[2*EE + t2]  : ac[3*EE + t2];
    }
    if (t == 0) out[OFF2 + b] = (float)(isn ? guid : guid_in[b]);
    if (t < CC) out[OFF3 + (size_t)b*CC + t] = isn ? (sLg[t] - sMax - sLse) : 0.f;
}

// ---------------------------------------------------------------------------
extern "C" void kernel_launch(void* const* d_in, const int* in_sizes, int n_in,
                              void* d_out, int out_size) {
    const float* depot = (const float*)d_in[0];
    const float* CE    = (const float*)d_in[1];
    const float* cur   = (const float*)d_in[2];
    const float* nodes = (const float*)d_in[3];
    const float* augc  = (const float*)d_in[4];
    const float* gein  = (const float*)d_in[5];
    const float* Wq    = (const float*)d_in[6];
    const float* Wk    = (const float*)d_in[7];
    const float* Wv    = (const float*)d_in[8];
    const float* Wks   = (const float*)d_in[9];
    const float* mWq   = (const float*)d_in[10];
    const float* mWk   = (const float*)d_in[11];
    const float* mWv   = (const float*)d_in[12];
    const float* Wo    = (const float*)d_in[13];
    const int* isnew   = (const int*)d_in[14];   // bool -> int32
    const int* mask    = (const int*)d_in[15];   // bool -> int32
    const int* cmask   = (const int*)d_in[16];   // bool -> int32
    const int* vcm     = (const int*)d_in[17];   // bool -> int32
    const int* guid    = (const int*)d_in[18];
    // d_in[19] = step (unused)

    dim3 gr(BB, SPLIT + 2);   // 8 reduce planes + 2 prep planes (768 rows)
    k_pre<<<gr, 128>>>(nodes, mask, cmask, Wq, Wk, Wv, Wks, Wo, mWq, mWk, mWv);
    k_main<<<BB, 256>>>(depot, CE, cur, augc, gein, isnew, vcm, guid,
                        (float*)d_out);
}

// round 11
// speedup vs baseline: 1.2165x; 1.2165x over previous
#include <cuda_runtime.h>
#include <cstdint>
#include <cmath>

#define BB 512
#define NN 1000
#define CC 50
#define CCP 51              // pitch for transposed cluster tile (odd -> conflict-free)
#define EE 128
#define HH 8
#define DD 16
#define SPLIT 8
#define NPS (NN/SPLIT)
#define NEGV (-1e9f)
#define FUSE_ROWS (6*EE)    // 768 rows of weight prep work

// scratch (no cudaMalloc allowed)
__device__ float g_part[BB*SPLIT*2*EE];   // [b][split][{mask, mask|cmask}][e]
__device__ float g_Wqf [3*EE*EE];         // Wq @ mha_Wq   (384 x 128), [i][j]
__device__ float g_WkfT[EE*EE];           // (Wk @ mha_Wk)^T : [j][e]
__device__ float g_Wvf [EE*EE];           // Wv @ mha_Wv    : [e][j]
__device__ float g_WoKs[EE*EE];           // Wo @ Wks^T     : [j][e]

// ---------------------------------------------------------------------------
// Kernel 1: masked reduction (predicated loads, 4-deep unroll) + weight prep
// folded into the same grid. grid (BB, SPLIT+2), 128 threads.
// ---------------------------------------------------------------------------
__global__ void __launch_bounds__(128) k_pre(
    const float* __restrict__ nodes,
    const int* __restrict__ mask, const int* __restrict__ cmask,
    const float* __restrict__ Wq, const float* __restrict__ Wk,
    const float* __restrict__ Wv, const float* __restrict__ Wks,
    const float* __restrict__ Wo,
    const float* __restrict__ mWq, const float* __restrict__ mWk,
    const float* __restrict__ mWv)
{
    const int b = blockIdx.x, y = blockIdx.y, t = threadIdx.x;
    const int warp = t >> 5, lane = t & 31;

    if (y >= SPLIT) {
        // ---- weight prep planes (overlap with reduction planes) ----
        int fr = (y - SPLIT)*BB + b;
        if (fr >= FUSE_ROWS) return;
        if (fr < 3*EE) {
            const float* a_ = Wq + fr*EE;
            float s0=0.f,s1=0.f,s2=0.f,s3=0.f;
            #pragma unroll 8
            for (int e = 0; e < EE; e += 4) {
                s0 += a_[e  ] * mWq[(e  )*EE + t];
                s1 += a_[e+1] * mWq[(e+1)*EE + t];
                s2 += a_[e+2] * mWq[(e+2)*EE + t];
                s3 += a_[e+3] * mWq[(e+3)*EE + t];
            }
            g_Wqf[fr*EE + t] = (s0+s1)+(s2+s3);
        } else if (fr < 4*EE) {
            const int e0 = fr - 3*EE;
            const float* a_ = Wk + e0*EE;
            float s0=0.f,s1=0.f,s2=0.f,s3=0.f;
            #pragma unroll 8
            for (int x = 0; x < EE; x += 4) {
                s0 += a_[x  ] * mWk[(x  )*EE + t];
                s1 += a_[x+1] * mWk[(x+1)*EE + t];
                s2 += a_[x+2] * mWk[(x+2)*EE + t];
                s3 += a_[x+3] * mWk[(x+3)*EE + t];
            }
            g_WkfT[t*EE + e0] = (s0+s1)+(s2+s3);   // transposed
        } else if (fr < 5*EE) {
            const int e0 = fr - 4*EE;
            const float* a_ = Wv + e0*EE;
            float s0=0.f,s1=0.f,s2=0.f,s3=0.f;
            #pragma unroll 8
            for (int x = 0; x < EE; x += 4) {
                s0 += a_[x  ] * mWv[(x  )*EE + t];
                s1 += a_[x+1] * mWv[(x+1)*EE + t];
                s2 += a_[x+2] * mWv[(x+2)*EE + t];
                s3 += a_[x+3] * mWv[(x+3)*EE + t];
            }
            g_Wvf[e0*EE + t] = (s0+s1)+(s2+s3);
        } else {
            // WoKs[j][e] = sum_f Wo[j][f] * Wks[e][f]  — tiled, coalesced
            const int j = fr - 5*EE;
            __shared__ float sWo[EE];
            __shared__ float sTile[32][EE + 1];   // [f-in-tile][e], odd pitch
            sWo[t] = Wo[j*EE + t];
            float acc = 0.f;
            for (int f0 = 0; f0 < EE; f0 += 32) {
                __syncthreads();
                // warp w loads rows e = w*32..w*32+31; lane reads consecutive f
                #pragma unroll 8
                for (int k = 0; k < 32; k++) {
                    int e = warp*32 + k;
                    sTile[lane][e] = Wks[e*EE + f0 + lane];   // coalesced 128B
                }
                __syncthreads();
                #pragma unroll 8
                for (int fi = 0; fi < 32; fi++)
                    acc += sWo[f0 + fi] * sTile[fi][t];       // conflict-free
            }
            g_WoKs[j*EE + t] = acc;
        }
        return;
    }

    // ---- reduction plane: rows [y*NPS, (y+1)*NPS) of batch b ----
    __shared__ uint8_t sM[NPS], sC[NPS];
    __shared__ float4  sR0[4][32], sR1[4][32];

    const int* m  = mask  + b*NN + y*NPS;
    const int* cm = cmask + b*NN + y*NPS;
    if (t < NPS) {
        sM[t] = (uint8_t)(m[t]  != 0);
        sC[t] = (uint8_t)(cm[t] != 0);
    }
    __syncthreads();

    const float4* base = (const float4*)(nodes + ((size_t)b*NN + (size_t)y*NPS)*EE);
    const float4  Z4 = make_float4(0.f,0.f,0.f,0.f);

    float4 a0 = Z4, a1 = Z4;
    int r = warp;
    // 4-deep: predicates + predicated loads issued before any accumulation
    for (; r + 12 < NPS; r += 16) {
        const bool k0 = !sM[r], k1 = !sM[r+4], k2 = !sM[r+8], k3 = !sM[r+12];
        float4 v0 = Z4, v1 = Z4, v2 = Z4, v3 = Z4;
        if (k0) v0 = __ldg(base + (r   )*32 + lane);
        if (k1) v1 = __ldg(base + (r+ 4)*32 + lane);
        if (k2) v2 = __ldg(base + (r+ 8)*32 + lane);
        if (k3) v3 = __ldg(base + (r+12)*32 + lane);
        a0.x += v0.x; a0.y += v0.y; a0.z += v0.z; a0.w += v0.w;
        a0.x += v1.x; a0.y += v1.y; a0.z += v1.z; a0.w += v1.w;
        a0.x += v2.x; a0.y += v2.y; a0.z += v2.z; a0.w += v2.w;
        a0.x += v3.x; a0.y += v3.y; a0.z += v3.z; a0.w += v3.w;
        if (k0 && !sC[r   ]) { a1.x += v0.x; a1.y += v0.y; a1.z += v0.z; a1.w += v0.w; }
        if (k1 && !sC[r+ 4]) { a1.x += v1.x; a1.y += v1.y; a1.z += v1.z; a1.w += v1.w; }
        if (k2 && !sC[r+ 8]) { a1.x += v2.x; a1.y += v2.y; a1.z += v2.z; a1.w += v2.w; }
        if (k3 && !sC[r+12]) { a1.x += v3.x; a1.y += v3.y; a1.z += v3.z; a1.w += v3.w; }
    }
    for (; r < NPS; r += 4) {
        const bool k0 = !sM[r];
        float4 v0 = Z4;
        if (k0) v0 = __ldg(base + r*32 + lane);
        a0.x += v0.x; a0.y += v0.y; a0.z += v0.z; a0.w += v0.w;
        if (k0 && !sC[r]) { a1.x += v0.x; a1.y += v0.y; a1.z += v0.z; a1.w += v0.w; }
    }
    sR0[warp][lane] = a0;
    sR1[warp][lane] = a1;
    __syncthreads();

    const float* p0 = (const float*)sR0;
    const float* p1 = (const float*)sR1;
    float s0 = p0[t] + p0[128 + t] + p0[256 + t] + p0[384 + t];
    float s1 = p1[t] + p1[128 + t] + p1[256 + t] + p1[384 + t];
    int idx = (b*SPLIT + y)*2*EE + t;
    g_part[idx]      = s0;
    g_part[idx + EE] = s1;
}

// ---------------------------------------------------------------------------
// Kernel 2: math chain per batch. 256 threads/block. (verified 37.5us form)
// ---------------------------------------------------------------------------
__global__ void __launch_bounds__(256) k_main(
    const float* __restrict__ depot, const float* __restrict__ CE,
    const float* __restrict__ cur,   const float* __restrict__ augc,
    const float* __restrict__ gein,
    const int* __restrict__ isnew, const int* __restrict__ vcm_g,
    const int* __restrict__ guid_in, float* __restrict__ out)
{
    const int b = blockIdx.x, t = threadIdx.x;
    const int t2 = t & 127, half = t >> 7;
    const int warp = t >> 5, lane = t & 31;

    __shared__ float sCET[EE*CCP];     // transposed cluster embeddings
    __shared__ float sCtx[3*EE];
    __shared__ float sUC[EE];
    __shared__ float sP2[2][EE];       // split-K partials (reused per stage)
    __shared__ float sQ[EE];
    __shared__ float sKQ[HH*EE];
    __shared__ float sSc[HH*CC];
    __shared__ float sAt[HH*CC];
    __shared__ float sAce[HH*EE];
    __shared__ float sGl[EE];
    __shared__ float sW2[EE];
    __shared__ float sLgP[4][CC];
    __shared__ float sLg[CC];
    __shared__ int   sVcm[CC];
    __shared__ float sMax, sLse;
    __shared__ int   sArg;

    // ---- load cluster embeddings transposed; half owns 25 c's, e = t2 ----
    {
        const float* src = CE + (size_t)b*CC*EE;
        #pragma unroll
        for (int cc = 0; cc < 25; cc++) {
            int c = half*25 + cc;
            sCET[t2*CCP + c] = src[c*EE + t2];
        }
    }

    // ---- combine reduction partials: half 0 -> um, half 1 -> uc ----
    {
        float a = 0.f;
        #pragma unroll
        for (int s = 0; s < SPLIT; s++)
            a += g_part[(b*SPLIT + s)*2*EE + half*EE + t2];
        a *= (1.f/NN);
        if (half == 0) sCtx[t2] = a; else sUC[t2] = a;
    }
    if (half == 0) sCtx[EE + t2]   = cur[b*EE + t2];
    else           sCtx[2*EE + t2] = depot[b*EE + t2];
    if (t < CC) sVcm[t] = (vcm_g[b*CC + t] != 0);
    __syncthreads();

    if (t == 0) {                      // vcm[0] = !all(vcm[1:])
        int all = 1;
        for (int c = 1; c < CC; c++) all &= (sVcm[c] != 0);
        sVcm[0] = !all;
    }

    // ---- q projection, split-K over halves (192 MACs each, 4 accs) ----
    {
        const int i0 = half*192;
        float a0=0.f,a1=0.f,a2=0.f,a3=0.f;
        #pragma unroll 4
        for (int i = 0; i < 192; i += 4) {
            a0 += sCtx[i0+i  ] * g_Wqf[(i0+i  )*EE + t2];
            a1 += sCtx[i0+i+1] * g_Wqf[(i0+i+1)*EE + t2];
            a2 += sCtx[i0+i+2] * g_Wqf[(i0+i+2)*EE + t2];
            a3 += sCtx[i0+i+3] * g_Wqf[(i0+i+3)*EE + t2];
        }
        sP2[half][t2] = (a0+a1)+(a2+a3);
    }
    __syncthreads();
    if (half == 0) sQ[t2] = sP2[0][t2] + sP2[1][t2];
    __syncthreads();

    // ---- kq[h][e]: 1024 outputs over 256 threads (4 each), 16 MACs ----
    #pragma unroll
    for (int k = 0; k < 4; k++) {
        int idx = t + 256*k;
        int h = idx >> 7, e = idx & 127;
        float a0=0.f,a1=0.f;
        #pragma unroll
        for (int d = 0; d < DD; d += 2) {
            a0 += sQ[h*DD + d  ] * g_WkfT[(h*DD + d  )*EE + e];
            a1 += sQ[h*DD + d+1] * g_WkfT[(h*DD + d+1)*EE + e];
        }
        sKQ[h*EE + e] = a0 + a1;
    }
    __syncthreads();

    // ---- scores: 400 outputs, 128 MACs, 4 accs ----
    for (int idx = t; idx < HH*CC; idx += 256) {
        int h = idx / CC, c = idx % CC;
        float a0=0.f,a1=0.f,a2=0.f,a3=0.f;
        #pragma unroll 4
        for (int e = 0; e < EE; e += 4) {
            a0 += sCET[(e  )*CCP + c] * sKQ[h*EE + e  ];
            a1 += sCET[(e+1)*CCP + c] * sKQ[h*EE + e+1];
            a2 += sCET[(e+2)*CCP + c] * sKQ[h*EE + e+2];
            a3 += sCET[(e+3)*CCP + c] * sKQ[h*EE + e+3];
        }
        float a = ((a0+a1)+(a2+a3)) * 0.25f;   // 1/sqrt(16)
        if (sVcm[c]) a = NEGV;
        sSc[h*CC + c] = a;
    }
    __syncthreads();

    // ---- softmax: warp h owns head h ----
    {
        int h = warp;
        float v0 = sSc[h*CC + lane];
        float v1 = (lane < CC-32) ? sSc[h*CC + lane + 32] : -3e38f;
        float mx = fmaxf(v0, v1);
        #pragma unroll
        for (int o = 16; o > 0; o >>= 1)
            mx = fmaxf(mx, __shfl_xor_sync(0xffffffffu, mx, o));
        float e0 = expf(v0 - mx);
        float e1 = (lane < CC-32) ? expf(v1 - mx) : 0.f;
        float sm = e0 + e1;
        #pragma unroll
        for (int o = 16; o > 0; o >>= 1)
            sm += __shfl_xor_sync(0xffffffffu, sm, o);
        float inv = 1.f / sm;
        sAt[h*CC + lane] = e0 * inv;
        if (lane < CC-32) sAt[h*CC + lane + 32] = e1 * inv;
    }
    __syncthreads();

    // ---- a_ce[h][e]: 1024 outputs over 256 threads, 50 MACs, 2 accs ----
    #pragma unroll
    for (int k = 0; k < 4; k++) {
        int idx = t + 256*k;
        int h = idx >> 7, e = idx & 127;
        float a0=0.f,a1=0.f;
        #pragma unroll 5
        for (int c = 0; c < CC; c += 2) {
            a0 += sAt[h*CC + c  ] * sCET[e*CCP + c  ];
            a1 += sAt[h*CC + c+1] * sCET[e*CCP + c+1];
        }
        sAce[h*EE + e] = a0 + a1;
    }
    __syncthreads();

    // ---- glimpse[j=t2]: 128-MAC split-K over halves (h = j/16) ----
    {
        int h = t2 / DD;
        const int e0 = half*64;
        float a0=0.f,a1=0.f,a2=0.f,a3=0.f;
        #pragma unroll 4
        for (int e = 0; e < 64; e += 4) {
            a0 += sAce[h*EE + e0+e  ] * g_Wvf[(e0+e  )*EE + t2];
            a1 += sAce[h*EE + e0+e+1] * g_Wvf[(e0+e+1)*EE + t2];
            a2 += sAce[h*EE + e0+e+2] * g_Wvf[(e0+e+2)*EE + t2];
            a3 += sAce[h*EE + e0+e+3] * g_Wvf[(e0+e+3)*EE + t2];
        }
        sP2[half][t2] = (a0+a1)+(a2+a3);
    }
    __syncthreads();
    if (half == 0) sGl[t2] = sP2[0][t2] + sP2[1][t2];
    __syncthreads();

    // ---- w2[e=t2] = sum_j gl[j] * WoKs[j][e]: split-K over halves ----
    {
        const int j0 = half*64;
        float a0=0.f,a1=0.f,a2=0.f,a3=0.f;
        #pragma unroll 4
        for (int j = 0; j < 64; j += 4) {
            a0 += sGl[j0+j  ] * g_WoKs[(j0+j  )*EE + t2];
            a1 += sGl[j0+j+1] * g_WoKs[(j0+j+1)*EE + t2];
            a2 += sGl[j0+j+2] * g_WoKs[(j0+j+2)*EE + t2];
            a3 += sGl[j0+j+3] * g_WoKs[(j0+j+3)*EE + t2];
        }
        sP2[half][t2] = (a0+a1)+(a2+a3);
    }
    __syncthreads();
    if (half == 0) sW2[t2] = sP2[0][t2] + sP2[1][t2];
    __syncthreads();

    // ---- logit[c]: 50 outputs, split over 4 quarters of e ----
    {
        int c = t & 63, q4 = t >> 6;
        if (c < CC) {
            const int e0 = q4*32;
            float a0=0.f,a1=0.f;
            #pragma unroll 4
            for (int e = 0; e < 32; e += 2) {
                a0 += sCET[(e0+e  )*CCP + c] * sW2[e0+e  ];
                a1 += sCET[(e0+e+1)*CCP + c] * sW2[e0+e+1];
            }
            sLgP[q4][c] = a0 + a1;
        }
    }
    __syncthreads();
    if (t < CC) {
        float a = (sLgP[0][t] + sLgP[1][t]) + (sLgP[2][t] + sLgP[3][t]);
        a *= 0.08838834764831845f;     // 1/sqrt(128)
        a = tanhf(a) * 10.f;
        if (sVcm[t]) a = NEGV;
        sLg[t] = a;
    }
    __syncthreads();

    // ---- argmax (first-index ties) + logsumexp, warp 0 via shfl ----
    if (warp == 0) {
        float v0 = sLg[lane];
        float v1 = (lane < CC-32) ? sLg[lane + 32] : -3e38f;
        float v = v0; int ix = lane;
        if (v1 > v) { v = v1; ix = lane + 32; }
        #pragma unroll
        for (int o = 16; o > 0; o >>= 1) {
            float ov = __shfl_xor_sync(0xffffffffu, v, o);
            int   oi = __shfl_xor_sync(0xffffffffu, ix, o);
            if (ov > v || (ov == v && oi < ix)) { v = ov; ix = oi; }
        }
        float mx = v;
        float sm = expf(v0 - mx) + ((lane < CC-32) ? expf(v1 - mx) : 0.f);
        #pragma unroll
        for (int o = 16; o > 0; o >>= 1)
            sm += __shfl_xor_sync(0xffffffffu, sm, o);
        if (lane == 0) { sMax = mx; sLse = logf(sm); sArg = ix; }
    }
    __syncthreads();

    const int  guid = sArg;
    const bool isn  = isnew[b] != 0;
    const float ge  = sCET[t2*CCP + guid];

    const size_t OFF1 = (size_t)BB*4*EE;            // guid_embed_out
    const size_t OFF2 = OFF1 + (size_t)BB*EE;       // guid_out
    const size_t OFF3 = OFF2 + BB;                  // clu_prob

    float* ao = out + (size_t)b*4*EE;
    const float* ac = augc + (size_t)b*4*EE;
    if (half == 0) {
        ao[t2]        = isn ? sUC[t2]          : ac[t2];
        ao[2*EE + t2] = isn ? ge               : ac[2*EE + t2];
        out[OFF1 + (size_t)b*EE + t2] = isn ? ge : gein[b*EE + t2];
    } else {
        ao[EE + t2]   = isn ? sCtx[EE + t2]    : ac[EE + t2];
        ao[3*EE + t2] = isn ? sCtx[2*EE + t2]  : ac[3*EE + t2];
    }
    if (t == 0) out[OFF2 + b] = (float)(isn ? guid : guid_in[b]);
    if (t < CC) out[OFF3 + (size_t)b*CC + t] = isn ? (sLg[t] - sMax - sLse) : 0.f;
}

// ---------------------------------------------------------------------------
extern "C" void kernel_launch(void* const* d_in, const int* in_sizes, int n_in,
                              void* d_out, int out_size) {
    const float* depot = (const float*)d_in[0];
    const float* CE    = (const float*)d_in[1];
    const float* cur   = (const float*)d_in[2];
    const float* nodes = (const float*)d_in[3];
    const float* augc  = (const float*)d_in[4];
    const float* gein  = (const float*)d_in[5];
    const float* Wq    = (const float*)d_in[6];
    const float* Wk    = (const float*)d_in[7];
    const float* Wv    = (const float*)d_in[8];
    const float* Wks   = (const float*)d_in[9];
    const float* mWq   = (const float*)d_in[10];
    const float* mWk   = (const float*)d_in[11];
    const float* mWv   = (const float*)d_in[12];
    const float* Wo    = (const float*)d_in[13];
    const int* isnew   = (const int*)d_in[14];   // bool -> int32
    const int* mask    = (const int*)d_in[15];   // bool -> int32
    const int* cmask   = (const int*)d_in[16];   // bool -> int32
    const int* vcm     = (const int*)d_in[17];   // bool -> int32
    const int* guid    = (const int*)d_in[18];
    // d_in[19] = step (unused)

    dim3 gr(BB, SPLIT + 2);   // 8 reduce planes + 2 prep planes (768 rows)
    k_pre<<<gr, 128>>>(nodes, mask, cmask, Wq, Wk, Wv, Wks, Wo, mWq, mWk, mWv);
    k_main<<<BB, 256>>>(depot, CE, cur, augc, gein, isnew, vcm, guid,
                        (float*)d_out);
}